// round 2
// baseline (speedup 1.0000x reference)
#include <cuda_runtime.h>
#include <cstdint>

// out[p] = (L >= 0) || (missing(p) - L >= 0.5), written as float 0.0/1.0
// where L = 7-point Laplacian (center*6 - 6 face neighbors, zero padding)
// and missing(p) = count of face neighbors outside the grid.
// Derivation: kernel sums to 0, so conv(1-m,k) = S(p) - conv(m,k) with
// S(p) = sum of in-bounds taps = missing-neighbor count.

#define DSZ 192

__global__ __launch_bounds__(384) void mask_kernel(
    const float* __restrict__ m, float* __restrict__ out)
{
    const int tx = threadIdx.x;                       // 0..47 -> x quad
    const int y  = blockIdx.y * blockDim.y + threadIdx.y;
    const int zb = blockIdx.z;
    const int z  = zb % DSZ;
    const int b  = zb / DSZ;
    const int x0 = tx * 4;

    const size_t plane = (size_t)DSZ * DSZ;
    const size_t rowbase = (((size_t)b * DSZ + z) * DSZ + y) * DSZ;
    const float* base = m + rowbase;

    const float4 zero4 = make_float4(0.f, 0.f, 0.f, 0.f);

    float4 c  = *(const float4*)(base + x0);
    float4 ym = (y > 0)       ? *(const float4*)(base - DSZ   + x0) : zero4;
    float4 yp = (y < DSZ - 1) ? *(const float4*)(base + DSZ   + x0) : zero4;
    float4 zm = (z > 0)       ? *(const float4*)(base - plane + x0) : zero4;
    float4 zp = (z < DSZ - 1) ? *(const float4*)(base + plane + x0) : zero4;
    float  xl = (x0 > 0)        ? __ldg(base + x0 - 1) : 0.f;
    float  xr = (x0 + 4 < DSZ)  ? __ldg(base + x0 + 4) : 0.f;

    float L0 = 6.f * c.x - (xl  + c.y + ym.x + yp.x + zm.x + zp.x);
    float L1 = 6.f * c.y - (c.x + c.z + ym.y + yp.y + zm.y + zp.y);
    float L2 = 6.f * c.z - (c.y + c.w + ym.z + yp.z + zm.z + zp.z);
    float L3 = 6.f * c.w - (c.z + xr  + ym.w + yp.w + zm.w + zp.w);

    const int missBase = (int)(y == 0) + (int)(y == DSZ - 1)
                       + (int)(z == 0) + (int)(z == DSZ - 1);
    const float miss0 = (float)(missBase + (int)(x0 == 0));
    const float miss3 = (float)(missBase + (int)(x0 + 4 == DSZ));
    const float fb = (float)missBase;

    float4 o;
    o.x = ((L0 >= 0.f) || (miss0 - L0 >= 0.5f)) ? 1.f : 0.f;
    o.y = ((L1 >= 0.f) || (fb    - L1 >= 0.5f)) ? 1.f : 0.f;
    o.z = ((L2 >= 0.f) || (fb    - L2 >= 0.5f)) ? 1.f : 0.f;
    o.w = ((L3 >= 0.f) || (miss3 - L3 >= 0.5f)) ? 1.f : 0.f;

    *(float4*)(out + rowbase + x0) = o;
}

extern "C" void kernel_launch(void* const* d_in, const int* in_sizes, int n_in,
                              void* d_out, int out_size)
{
    const float* m = (const float*)d_in[0];
    float* out = (float*)d_out;

    dim3 block(48, 8, 1);                 // 384 threads: full 192-wide row x 8 rows
    dim3 grid(1, DSZ / 8, 2 * DSZ);       // y-tiles, z * batch
    mask_kernel<<<grid, block>>>(m, out);
}